// round 14
// baseline (speedup 1.0000x reference)
#include <cuda_runtime.h>
#include <math.h>

// Problem constants
#define Bb 2
#define Cc 64
#define Nn 8192
#define Oo 64
#define Kk 20
#define NPOINTS (Bb * Nn)            // 16384
#define MROWS   (NPOINTS * Kk)       // 327680
#define NBLK_CONV (MROWS / 160)      // 2048
#define CAND_CAP 1536
#define SEG 24                       // slots per (row, column-tile) segment
#define NTILE 64                     // column tiles per row

// ---------------- scratch (device globals; allocation-free) ----------------
__device__ float  g_xt[NPOINTS * Cc];   // [B*N][C]   transposed points
__device__ float  g_sq[NPOINTS];        // ||x||^2 per point
__device__ float  g_xsT[Bb * Cc * 256]; // gathered sample points, [b][c][s]
__device__ float  g_sqs[Bb * 256];      // sample sq
__device__ float  g_sdist[NPOINTS * 256]; // sample distances per row
__device__ float  g_thr[NPOINTS];       // per-row threshold
__device__ float  g_candv[(size_t)NPOINTS * CAND_CAP];
__device__ int    g_candi[(size_t)NPOINTS * CAND_CAP];
__device__ int    g_tc[NPOINTS * NTILE]; // per (row, tile) survivor count
__device__ int    g_idx[MROWS];         // top-K indices, [B*N][K]
__device__ float  g_u[NPOINTS * Oo];    // center term (W2-W1)·cen
__device__ double g_sum[Oo];
__device__ double g_sumsq[Oo];
__device__ float  g_sc[Oo];
__device__ float  g_sh[Oo];

// monotonic float <-> sortable uint mapping
__device__ __forceinline__ unsigned f2key(float f) {
    unsigned u = __float_as_uint(f);
    return (u & 0x80000000u) ? ~u : (u | 0x80000000u);
}
__device__ __forceinline__ float key2f(unsigned m) {
    return __uint_as_float((m & 0x80000000u) ? (m & 0x7FFFFFFFu) : ~m);
}

// ---------------- packed fp32x2 helpers (B300 FFMA2 path, PTX-only) --------
__device__ __forceinline__ unsigned long long dup2(float a) {
    unsigned long long r;
    asm("mov.b64 %0, {%1, %1};" : "=l"(r) : "f"(a));
    return r;
}
__device__ __forceinline__ void fma2(unsigned long long& d, unsigned long long a,
                                     unsigned long long b) {
    asm("fma.rn.f32x2 %0, %1, %2, %0;" : "+l"(d) : "l"(a), "l"(b));
}
__device__ __forceinline__ float2 unpk(unsigned long long v) {
    float2 r;
    asm("mov.b64 {%0, %1}, %2;" : "=f"(r.x), "=f"(r.y) : "l"(v));
    return r;
}

// ---------------- kernel 0: init candidate slots (-INF) + accumulators ----
__global__ void k_zero() {
    const size_t total4 = (size_t)NPOINTS * CAND_CAP / 4;
    float4 ninf = make_float4(-INFINITY, -INFINITY, -INFINITY, -INFINITY);
    for (size_t t = (size_t)blockIdx.x * 256 + threadIdx.x; t < total4;
         t += (size_t)gridDim.x * 256)
        ((float4*)g_candv)[t] = ninf;
    if (blockIdx.x == 0 && threadIdx.x < Oo) {
        g_sum[threadIdx.x] = 0.0; g_sumsq[threadIdx.x] = 0.0;
    }
}

// ---------------- kernel 1: transpose x -> xt, sq, gather samples ---------
// Sample positions: pos(s) = s*32 + (s&31), s in [0,256).
__global__ void k_prep(const float* __restrict__ x) {
    int p = blockIdx.x * 256 + threadIdx.x;   // 0..16383
    int b = p >> 13;
    int n = p & (Nn - 1);
    const float* xb = x + (size_t)b * Cc * Nn;
    bool is_s = ((n & 31) == ((n >> 5) & 31));
    int s = n >> 5;
    float sm = 0.f;
    #pragma unroll
    for (int c = 0; c < Cc; c++) {
        float v = xb[c * Nn + n];
        sm += v * v;
        g_xt[(size_t)p * Cc + c] = v;
        if (is_s) g_xsT[(b * Cc + c) * 256 + s] = v;
    }
    g_sq[p] = sm;
    if (is_s) g_sqs[b * 256 + s] = sm;
}

// ---------------- kernel 2a: sample-dist GEMM (rows x 256 samples) --------
#define DSTRIDE 132
__global__ void k_samp(const float* __restrict__ x) {
    extern __shared__ float sm[];
    float* As = sm;
    float* Bs = sm + 64 * DSTRIDE;
    const int b  = blockIdx.z;
    const int i0 = blockIdx.y * 128;
    const int j0 = blockIdx.x * 128;
    const int tid = threadIdx.x;
    const float* xb = x + (size_t)b * Cc * Nn;

    for (int L = tid; L < 2048; L += 256) {
        int c = L >> 5, q = L & 31;
        float4 v = *(const float4*)(xb + c * Nn + i0 + q * 4);
        *(float4*)(As + c * DSTRIDE + q * 4) = v;
        float4 w = *(const float4*)(g_xsT + (b * Cc + c) * 256 + j0 + q * 4);
        *(float4*)(Bs + c * DSTRIDE + q * 4) = w;
    }
    __syncthreads();

    int tx = tid & 15, ty = tid >> 4;
    unsigned long long acc2[8][4];
    #pragma unroll
    for (int i = 0; i < 8; i++)
        #pragma unroll
        for (int q = 0; q < 4; q++) acc2[i][q] = 0ull;

    #pragma unroll 4
    for (int kk = 0; kk < 64; kk++) {
        ulonglong2 bb0 = *(const ulonglong2*)(Bs + kk * DSTRIDE + tx * 8);
        ulonglong2 bb1 = *(const ulonglong2*)(Bs + kk * DSTRIDE + tx * 8 + 4);
        float4 a0 = *(const float4*)(As + kk * DSTRIDE + ty * 8);
        float4 a1 = *(const float4*)(As + kk * DSTRIDE + ty * 8 + 4);
        float a[8] = {a0.x, a0.y, a0.z, a0.w, a1.x, a1.y, a1.z, a1.w};
        #pragma unroll
        for (int i = 0; i < 8; i++) {
            unsigned long long ap = dup2(a[i]);
            fma2(acc2[i][0], ap, bb0.x);
            fma2(acc2[i][1], ap, bb0.y);
            fma2(acc2[i][2], ap, bb1.x);
            fma2(acc2[i][3], ap, bb1.y);
        }
    }

    float sqj[8];
    #pragma unroll
    for (int j = 0; j < 8; j++) sqj[j] = g_sqs[b * 256 + j0 + tx * 8 + j];
    #pragma unroll
    for (int i = 0; i < 8; i++) {
        float sqi = g_sq[b * Nn + i0 + ty * 8 + i];
        float* dst = g_sdist + (size_t)(b * Nn + i0 + ty * 8 + i) * 256 + j0 + tx * 8;
        float2 p0 = unpk(acc2[i][0]);
        float2 p1 = unpk(acc2[i][1]);
        float2 p2 = unpk(acc2[i][2]);
        float2 p3 = unpk(acc2[i][3]);
        float4 r0, r1;
        r0.x = 2.f * p0.x - sqi - sqj[0];
        r0.y = 2.f * p0.y - sqi - sqj[1];
        r0.z = 2.f * p1.x - sqi - sqj[2];
        r0.w = 2.f * p1.y - sqi - sqj[3];
        r1.x = 2.f * p2.x - sqi - sqj[4];
        r1.y = 2.f * p2.y - sqi - sqj[5];
        r1.z = 2.f * p3.x - sqi - sqj[6];
        r1.w = 2.f * p3.y - sqi - sqj[7];
        *(float4*)dst = r0;
        *(float4*)(dst + 4) = r1;
    }
}

// ---------------- kernel 2b: per-row threshold = 12th largest sample ------
__global__ __launch_bounds__(256) void k_thr() {
    int lane = threadIdx.x & 31;
    int row  = blockIdx.x * 8 + (threadIdx.x >> 5);
    const float* sd = g_sdist + (size_t)row * 256;
    float lv[8];
    #pragma unroll
    for (int s = 0; s < 8; s++) lv[s] = sd[lane + 32 * s];
    for (int k = 0; ; k++) {
        float lmax = lv[0];
        #pragma unroll
        for (int s = 1; s < 8; s++) lmax = fmaxf(lmax, lv[s]);
        unsigned key = f2key(lmax);
        unsigned m = __reduce_max_sync(0xffffffffu, key);
        if (k == 11) { if (lane == 0) g_thr[row] = key2f(m); break; }
        int win = __ffs(__ballot_sync(0xffffffffu, key == m)) - 1;
        if (lane == win) {
            bool done = false;
            #pragma unroll
            for (int s = 0; s < 8; s++)
                if (!done && lv[s] == lmax) { lv[s] = -INFINITY; done = true; }
        }
    }
}

// ---------------- kernel 3: symmetric dist GEMM + fixed-slot filter -------
// Upper-triangle tiles only (jb >= ib). After the mainloop, the 2*acc tile
// is staged in smem (stride 129: conflict-free row AND column reads). Each
// warp scans 16 rows (i-side) and 16 columns (j-side), writing survivors
// directly to reserved per-(row,tile) global slots: tile tj of row in block
// bi is owned by block (bi,tj) i-side if tj>=bi, else (tj,bi) j-side —
// exactly one writer per segment, so NO atomics anywhere.
#define VST 129
__global__ __launch_bounds__(256) void k_dist_sym(const float* __restrict__ x) {
    extern __shared__ float sm[];
    float* As = sm;
    float* Bs = sm + 64 * DSTRIDE;
    __shared__ float s_thri[128], s_thrj[128], s_sqi[128], s_sqj[128];

    const int b  = blockIdx.z;
    const int ib = blockIdx.y;
    const int jb = blockIdx.x;
    if (jb < ib) return;
    const int i0 = ib * 128;
    const int j0 = jb * 128;
    const bool diag = (ib == jb);
    const int tid  = threadIdx.x;
    const int wid  = tid >> 5;
    const int lane = tid & 31;
    const float* xb = x + (size_t)b * Cc * Nn;

    for (int L = tid; L < 2048; L += 256) {
        int c = L >> 5, q = L & 31;
        float4 v = *(const float4*)(xb + c * Nn + i0 + q * 4);
        *(float4*)(As + c * DSTRIDE + q * 4) = v;
        float4 w = *(const float4*)(xb + c * Nn + j0 + q * 4);
        *(float4*)(Bs + c * DSTRIDE + q * 4) = w;
    }
    if (tid < 128) {
        s_thri[tid] = g_thr[b * Nn + i0 + tid];
        s_sqi[tid]  = g_sq [b * Nn + i0 + tid];
    } else {
        int t = tid - 128;
        s_thrj[t] = g_thr[b * Nn + j0 + t];
        s_sqj[t]  = g_sq [b * Nn + j0 + t];
    }
    __syncthreads();

    int tx = tid & 15, ty = tid >> 4;
    unsigned long long acc2[8][4];
    #pragma unroll
    for (int i = 0; i < 8; i++)
        #pragma unroll
        for (int q = 0; q < 4; q++) acc2[i][q] = 0ull;

    #pragma unroll 4
    for (int kk = 0; kk < 64; kk++) {
        ulonglong2 bb0 = *(const ulonglong2*)(Bs + kk * DSTRIDE + tx * 8);
        ulonglong2 bb1 = *(const ulonglong2*)(Bs + kk * DSTRIDE + tx * 8 + 4);
        float4 a0 = *(const float4*)(As + kk * DSTRIDE + ty * 8);
        float4 a1 = *(const float4*)(As + kk * DSTRIDE + ty * 8 + 4);
        float a[8] = {a0.x, a0.y, a0.z, a0.w, a1.x, a1.y, a1.z, a1.w};
        #pragma unroll
        for (int i = 0; i < 8; i++) {
            unsigned long long ap = dup2(a[i]);
            fma2(acc2[i][0], ap, bb0.x);
            fma2(acc2[i][1], ap, bb0.y);
            fma2(acc2[i][2], ap, bb1.x);
            fma2(acc2[i][3], ap, bb1.y);
        }
    }

    // stage 2*acc tile into smem (reuse As/Bs; 128*129 <= 2*64*132)
    __syncthreads();
    float* Vs = sm;
    #pragma unroll
    for (int i = 0; i < 8; i++) {
        int rl = ty * 8 + i;
        float2 q0 = unpk(acc2[i][0]);
        float2 q1 = unpk(acc2[i][1]);
        float2 q2 = unpk(acc2[i][2]);
        float2 q3 = unpk(acc2[i][3]);
        float* vr = Vs + rl * VST + tx * 8;
        vr[0] = 2.f * q0.x; vr[1] = 2.f * q0.y;
        vr[2] = 2.f * q1.x; vr[3] = 2.f * q1.y;
        vr[4] = 2.f * q2.x; vr[5] = 2.f * q2.y;
        vr[6] = 2.f * q3.x; vr[7] = 2.f * q3.y;
    }
    __syncthreads();

    // i-side: warp scans rows wid*16..+15 (this block owns segment jb)
    for (int rr = 0; rr < 16; rr++) {
        int r = wid * 16 + rr;
        float sqi = s_sqi[r], thr = s_thri[r];
        float v[4]; unsigned msk[4]; int pc[4];
        int cnt = 0;
        #pragma unroll
        for (int s = 0; s < 4; s++) {
            int c = lane + 32 * s;
            float t2 = Vs[r * VST + c];
            v[s] = (t2 - sqi) - s_sqj[c];
            msk[s] = __ballot_sync(0xffffffffu, v[s] > thr);
            pc[s] = cnt; cnt += __popc(msk[s]);
        }
        int grow = b * Nn + i0 + r;
        if (lane == 0) g_tc[grow * NTILE + jb] = cnt;
        if (cnt) {
            size_t base = (size_t)grow * CAND_CAP + jb * SEG;
            #pragma unroll
            for (int s = 0; s < 4; s++) {
                if ((msk[s] >> lane) & 1u) {
                    int pos = pc[s] + __popc(msk[s] & ((1u << lane) - 1u));
                    if (pos < SEG) {
                        g_candv[base + pos] = v[s];
                        g_candi[base + pos] = j0 + lane + 32 * s;
                    }
                }
            }
        }
    }

    // j-side: warp scans columns wid*16..+15 (this block owns segment ib)
    if (!diag) {
        for (int cc = 0; cc < 16; cc++) {
            int c = wid * 16 + cc;
            float sqj = s_sqj[c], thr = s_thrj[c];
            float v[4]; unsigned msk[4]; int pc[4];
            int cnt = 0;
            #pragma unroll
            for (int s = 0; s < 4; s++) {
                int r = lane + 32 * s;
                float t2 = Vs[r * VST + c];
                v[s] = (t2 - sqj) - s_sqi[r];
                msk[s] = __ballot_sync(0xffffffffu, v[s] > thr);
                pc[s] = cnt; cnt += __popc(msk[s]);
            }
            int grow = b * Nn + j0 + c;
            if (lane == 0) g_tc[grow * NTILE + ib] = cnt;
            if (cnt) {
                size_t base = (size_t)grow * CAND_CAP + ib * SEG;
                #pragma unroll
                for (int s = 0; s < 4; s++) {
                    if ((msk[s] >> lane) & 1u) {
                        int pos = pc[s] + __popc(msk[s] & ((1u << lane) - 1u));
                        if (pos < SEG) {
                            g_candv[base + pos] = v[s];
                            g_candi[base + pos] = i0 + lane + 32 * s;
                        }
                    }
                }
            }
        }
    }
}

// ---------------- kernel 4: top-20 select (warp/row, smem-staged) ---------
__global__ __launch_bounds__(256) void k_sel() {
    __shared__ float svv[8][CAND_CAP];
    int lane = threadIdx.x & 31;
    int w    = threadIdx.x >> 5;
    int row  = blockIdx.x * 8 + w;

    // total survivors + overflow detection from segment counts
    int n = 0; bool ovf = false;
    for (int t = lane; t < NTILE; t += 32) {
        int c = g_tc[row * NTILE + t];
        n += c;
        if (c > SEG) ovf = true;
    }
    n = __reduce_add_sync(0xffffffffu, n);
    ovf = __any_sync(0xffffffffu, ovf);

    if (!ovf && n >= Kk) {
        size_t rb = (size_t)row * CAND_CAP;
        float* cv = svv[w];
        for (int c = lane; c < CAND_CAP; c += 32) cv[c] = g_candv[rb + c];
        __syncwarp();
        const int nseg = CAND_CAP / 32;   // 48; empty slots are -INF
        float bv = -INFINITY; int bs = -1;
        #pragma unroll 8
        for (int s = 0; s < nseg; s++) {
            int c = lane + (s << 5);
            float vv = cv[c];
            if (vv > bv) { bv = vv; bs = c; }
        }
        for (int k = 0; k < Kk; k++) {
            unsigned key = f2key(bv);
            unsigned m = __reduce_max_sync(0xffffffffu, key);
            int cand = (key == m && bs >= 0) ? g_candi[rb + bs] : 0x7fffffff;
            int widx = __reduce_min_sync(0xffffffffu, cand);
            if (lane == 0) g_idx[row * Kk + k] = widx;
            if (cand == widx) {
                cv[bs] = -INFINITY;
                bv = -INFINITY; bs = -1;
                #pragma unroll 8
                for (int s = 0; s < nseg; s++) {
                    int c = lane + (s << 5);
                    float vv = cv[c];
                    if (vv > bv) { bv = vv; bs = c; }
                }
            }
        }
    } else {
        // exact warp-local fallback: recompute the row (never runs in practice)
        int base = (row >> 13) * Nn;
        const float* xq = g_xt + (size_t)row * Cc;
        float sqq = g_sq[row];
        int chosen[Kk];
        for (int k = 0; k < Kk; k++) {
            float bv = -INFINITY; int bi = 0x7fffffff;
            for (int j = lane; j < Nn; j += 32) {
                bool skip = false;
                for (int q = 0; q < k; q++) if (chosen[q] == j) skip = true;
                if (skip) continue;
                const float* xj = g_xt + (size_t)(base + j) * Cc;
                float dot = 0.f;
                #pragma unroll
                for (int c = 0; c < Cc; c++) dot += xq[c] * xj[c];
                float val = 2.f * dot - sqq - g_sq[base + j];
                if (val > bv) { bv = val; bi = j; }
            }
            unsigned key = f2key(bv);
            unsigned m = __reduce_max_sync(0xffffffffu, key);
            int cand = (key == m) ? bi : 0x7fffffff;
            int widx = __reduce_min_sync(0xffffffffu, cand);
            if (lane == 0) g_idx[row * Kk + k] = widx;
            chosen[k] = widx;
        }
    }
}

// ---------------- kernel 5: center term u = (W[:,C:]-W[:,:C]) . cen -------
__global__ void k_u(const float* __restrict__ W) {
    __shared__ float Wd[64 * 65];   // [c][o], stride 65 (conflict-free)
    __shared__ float cs[4 * 64];
    int tid = threadIdx.x;
    for (int L = tid; L < 4096; L += 256) {
        int c = L & 63, o = L >> 6;
        Wd[c * 65 + o] = W[o * 128 + 64 + c] - W[o * 128 + c];
    }
    int p0 = blockIdx.x * 4;
    {
        int pi = tid >> 6, c = tid & 63;
        cs[pi * 64 + c] = g_xt[(size_t)(p0 + pi) * 64 + c];
    }
    __syncthreads();
    int o = tid & 63, pi = tid >> 6;
    float a = 0.f;
    #pragma unroll
    for (int c = 0; c < 64; c++) a += Wd[c * 65 + o] * cs[pi * 64 + c];
    g_u[(size_t)(p0 + pi) * 64 + o] = a;
}

// ---------------- kernel 6/8: gathered GEMM  h = A·nbr + u ----------------
#define SA 161
#define WS_OFF 10400   // floats (41600 B region for As/hbuf)
template<int MODE>
__global__ void k_conv(const float* __restrict__ W, float* __restrict__ out) {
    extern __shared__ float sm[];
    float* As = sm;            // [64][161]  (MODE1: reused as hbuf [160][65])
    float* Ws = sm + WS_OFF;   // [64][68]
    __shared__ int   rowb[160];
    __shared__ int   ub[160];
    __shared__ float ssum[64];
    __shared__ float ssq[64];
    __shared__ float ssc[64];
    __shared__ float ssh[64];

    int tid = threadIdx.x;
    int m0 = blockIdx.x * 160;

    if (tid < 160) {
        int m = m0 + tid;
        int nb = g_idx[m];
        int pt = m / Kk;           // global point index b*N+n
        int b  = pt >> 13;
        rowb[tid] = b * Nn + nb;   // gathered xt row
        ub[tid]   = pt;            // u row
    }
    for (int L = tid; L < 4096; L += 256) {
        int c = L & 63, o = L >> 6;
        Ws[c * 68 + o] = W[o * 128 + c];   // A part, K-major
    }
    if (MODE == 0) { if (tid < 64) { ssum[tid] = 0.f; ssq[tid] = 0.f; } }
    else           { if (tid < 64) { ssc[tid] = g_sc[tid]; ssh[tid] = g_sh[tid]; } }
    __syncthreads();

    for (int L = tid; L < 2560; L += 256) {
        int r = L >> 4, c4 = L & 15;
        float4 v = *(const float4*)(g_xt + (size_t)rowb[r] * 64 + c4 * 4);
        As[(c4 * 4 + 0) * SA + r] = v.x;
        As[(c4 * 4 + 1) * SA + r] = v.y;
        As[(c4 * 4 + 2) * SA + r] = v.z;
        As[(c4 * 4 + 3) * SA + r] = v.w;
    }
    __syncthreads();

    int tx = tid & 7, ty = tid >> 3;   // tx: 8 col-groups, ty: 32 row-groups
    float acc[5][8];
    #pragma unroll
    for (int i = 0; i < 5; i++)
        #pragma unroll
        for (int j = 0; j < 8; j++) acc[i][j] = 0.f;

    #pragma unroll 4
    for (int kk = 0; kk < 64; kk++) {
        float a[5];
        #pragma unroll
        for (int i = 0; i < 5; i++) a[i] = As[kk * SA + ty * 5 + i];
        float4 b0 = *(float4*)(Ws + kk * 68 + tx * 8);
        float4 b1 = *(float4*)(Ws + kk * 68 + tx * 8 + 4);
        float bbv[8] = {b0.x, b0.y, b0.z, b0.w, b1.x, b1.y, b1.z, b1.w};
        #pragma unroll
        for (int i = 0; i < 5; i++)
            #pragma unroll
            for (int j = 0; j < 8; j++) acc[i][j] += a[i] * bbv[j];
    }

    // add center term
    float hv[5][8];
    #pragma unroll
    for (int i = 0; i < 5; i++) {
        const float* up = g_u + (size_t)ub[ty * 5 + i] * 64 + tx * 8;
        float4 u0 = *(const float4*)up;
        float4 u1 = *(const float4*)(up + 4);
        float uv[8] = {u0.x, u0.y, u0.z, u0.w, u1.x, u1.y, u1.z, u1.w};
        #pragma unroll
        for (int j = 0; j < 8; j++) hv[i][j] = acc[i][j] + uv[j];
    }

    if (MODE == 0) {
        float ps[8], pq[8];
        #pragma unroll
        for (int j = 0; j < 8; j++) { ps[j] = 0.f; pq[j] = 0.f; }
        #pragma unroll
        for (int i = 0; i < 5; i++)
            #pragma unroll
            for (int j = 0; j < 8; j++) {
                float v = hv[i][j];
                ps[j] += v; pq[j] += v * v;
            }
        #pragma unroll
        for (int j = 0; j < 8; j++) {
            atomicAdd(&ssum[tx * 8 + j], ps[j]);
            atomicAdd(&ssq [tx * 8 + j], pq[j]);
        }
        __syncthreads();
        if (tid < 64) {
            atomicAdd(&g_sum[tid],   (double)ssum[tid]);
            atomicAdd(&g_sumsq[tid], (double)ssq[tid]);
        }
    } else {
        __syncthreads();  // As fully consumed; safe to reuse as hbuf
        #pragma unroll
        for (int i = 0; i < 5; i++)
            #pragma unroll
            for (int j = 0; j < 8; j++) {
                int o = tx * 8 + j;
                float v = hv[i][j] * ssc[o] + ssh[o];
                v = (v >= 0.f) ? v : 0.2f * v;
                As[(ty * 5 + i) * 65 + o] = v;
            }
        __syncthreads();
        for (int task = tid; task < 512; task += 256) {
            int p = task >> 6, o = task & 63;
            float mx = -INFINITY;
            #pragma unroll
            for (int k = 0; k < Kk; k++)
                mx = fmaxf(mx, As[(p * Kk + k) * 65 + o]);
            int pt = m0 / Kk + p;
            int b = pt >> 13, n = pt & (Nn - 1);
            out[((size_t)b * 64 + o) * Nn + n] = mx;
        }
    }
}

// ---------------- kernel 7: finalize BN scale/shift ----------------
__global__ void k_fin(const float* __restrict__ gamma, const float* __restrict__ beta) {
    int o = threadIdx.x;
    if (o < Oo) {
        double cnt  = (double)MROWS;
        double mean = g_sum[o] / cnt;
        double var  = g_sumsq[o] / cnt - mean * mean;
        float inv = rsqrtf((float)(var + 1e-5));
        float sc  = gamma[o] * inv;
        g_sc[o] = sc;
        g_sh[o] = beta[o] - (float)mean * sc;
    }
}

// ---------------- launcher ----------------
extern "C" void kernel_launch(void* const* d_in, const int* in_sizes, int n_in,
                              void* d_out, int out_size) {
    const float* x     = (const float*)d_in[0];
    const float* W     = (const float*)d_in[1];
    const float* gamma = (const float*)d_in[2];
    const float* beta  = (const float*)d_in[3];
    float* out = (float*)d_out;

    const int SMEM_GEMM = 2 * 64 * DSTRIDE * sizeof(float);          // 67584
    const int SMEM_CONV = (WS_OFF + 64 * 68) * sizeof(float);        // 59008

    cudaFuncSetAttribute(k_samp,     cudaFuncAttributeMaxDynamicSharedMemorySize, SMEM_GEMM);
    cudaFuncSetAttribute(k_dist_sym, cudaFuncAttributeMaxDynamicSharedMemorySize, SMEM_GEMM);
    cudaFuncSetAttribute(k_conv<0>,  cudaFuncAttributeMaxDynamicSharedMemorySize, SMEM_CONV);
    cudaFuncSetAttribute(k_conv<1>,  cudaFuncAttributeMaxDynamicSharedMemorySize, SMEM_CONV);

    k_zero<<<4096, 256>>>();
    k_prep<<<NPOINTS / 256, 256>>>(x);
    k_samp<<<dim3(2, Nn / 128, Bb), 256, SMEM_GEMM>>>(x);
    k_thr<<<NPOINTS / 8, 256>>>();
    k_dist_sym<<<dim3(Nn / 128, Nn / 128, Bb), 256, SMEM_GEMM>>>(x);
    k_sel<<<NPOINTS / 8, 256>>>();
    k_u<<<NPOINTS / 4, 256>>>(W);
    k_conv<0><<<NBLK_CONV, 256, SMEM_CONV>>>(W, out);
    k_fin<<<1, 64>>>(gamma, beta);
    k_conv<1><<<NBLK_CONV, 256, SMEM_CONV>>>(W, out);
}

// round 15
// speedup vs baseline: 10.7601x; 10.7601x over previous
#include <cuda_runtime.h>
#include <math.h>

// Problem constants
#define Bb 2
#define Cc 64
#define Nn 8192
#define Oo 64
#define Kk 20
#define NPOINTS (Bb * Nn)            // 16384
#define MROWS   (NPOINTS * Kk)       // 327680
#define NBLK_CONV (MROWS / 160)      // 2048
#define SEG 48                       // slots per (row, column-tile) segment
#define NTILE 64                     // column tiles per row
#define CAND_SLOTS (NTILE * SEG)     // 3072 slots per row
#define DCAP 1536                    // dense per-row candidate cap in k_sel

// ---------------- scratch (device globals; allocation-free) ----------------
__device__ float  g_xt[NPOINTS * Cc];   // [B*N][C]   transposed points
__device__ float  g_sq[NPOINTS];        // ||x||^2 per point
__device__ float  g_xsT[Bb * Cc * 256]; // gathered sample points, [b][c][s]
__device__ float  g_sqs[Bb * 256];      // sample sq
__device__ float  g_sdist[NPOINTS * 256]; // sample distances per row
__device__ float  g_thr[NPOINTS];       // per-row threshold
__device__ float  g_candv[(size_t)NPOINTS * CAND_SLOTS];
__device__ int    g_candi[(size_t)NPOINTS * CAND_SLOTS];
__device__ int    g_tc[NPOINTS * NTILE]; // per (row, tile) survivor count
__device__ int    g_idx[MROWS];         // top-K indices, [B*N][K]
__device__ float  g_u[NPOINTS * Oo];    // center term (W2-W1)·cen
__device__ double g_sum[Oo];
__device__ double g_sumsq[Oo];
__device__ float  g_sc[Oo];
__device__ float  g_sh[Oo];

// monotonic float <-> sortable uint mapping
__device__ __forceinline__ unsigned f2key(float f) {
    unsigned u = __float_as_uint(f);
    return (u & 0x80000000u) ? ~u : (u | 0x80000000u);
}
__device__ __forceinline__ float key2f(unsigned m) {
    return __uint_as_float((m & 0x80000000u) ? (m & 0x7FFFFFFFu) : ~m);
}

// ---------------- packed fp32x2 helpers (B300 FFMA2 path, PTX-only) --------
__device__ __forceinline__ unsigned long long dup2(float a) {
    unsigned long long r;
    asm("mov.b64 %0, {%1, %1};" : "=l"(r) : "f"(a));
    return r;
}
__device__ __forceinline__ void fma2(unsigned long long& d, unsigned long long a,
                                     unsigned long long b) {
    asm("fma.rn.f32x2 %0, %1, %2, %0;" : "+l"(d) : "l"(a), "l"(b));
}
__device__ __forceinline__ float2 unpk(unsigned long long v) {
    float2 r;
    asm("mov.b64 {%0, %1}, %2;" : "=f"(r.x), "=f"(r.y) : "l"(v));
    return r;
}

// ---------------- kernel 0: zero accumulators ----------------
__global__ void k_zero() {
    int t = threadIdx.x;
    if (t < Oo) { g_sum[t] = 0.0; g_sumsq[t] = 0.0; }
}

// ---------------- kernel 1: transpose x -> xt, sq, gather samples ---------
// Sample positions: pos(s) = s*32 + (s&31), s in [0,256).
__global__ void k_prep(const float* __restrict__ x) {
    int p = blockIdx.x * 256 + threadIdx.x;   // 0..16383
    int b = p >> 13;
    int n = p & (Nn - 1);
    const float* xb = x + (size_t)b * Cc * Nn;
    bool is_s = ((n & 31) == ((n >> 5) & 31));
    int s = n >> 5;
    float sm = 0.f;
    #pragma unroll
    for (int c = 0; c < Cc; c++) {
        float v = xb[c * Nn + n];
        sm += v * v;
        g_xt[(size_t)p * Cc + c] = v;
        if (is_s) g_xsT[(b * Cc + c) * 256 + s] = v;
    }
    g_sq[p] = sm;
    if (is_s) g_sqs[b * 256 + s] = sm;
}

// ---------------- kernel 2a: sample-dist GEMM (rows x 256 samples) --------
#define DSTRIDE 132
__global__ void k_samp(const float* __restrict__ x) {
    extern __shared__ float sm[];
    float* As = sm;
    float* Bs = sm + 64 * DSTRIDE;
    const int b  = blockIdx.z;
    const int i0 = blockIdx.y * 128;
    const int j0 = blockIdx.x * 128;
    const int tid = threadIdx.x;
    const float* xb = x + (size_t)b * Cc * Nn;

    for (int L = tid; L < 2048; L += 256) {
        int c = L >> 5, q = L & 31;
        float4 v = *(const float4*)(xb + c * Nn + i0 + q * 4);
        *(float4*)(As + c * DSTRIDE + q * 4) = v;
        float4 w = *(const float4*)(g_xsT + (b * Cc + c) * 256 + j0 + q * 4);
        *(float4*)(Bs + c * DSTRIDE + q * 4) = w;
    }
    __syncthreads();

    int tx = tid & 15, ty = tid >> 4;
    unsigned long long acc2[8][4];
    #pragma unroll
    for (int i = 0; i < 8; i++)
        #pragma unroll
        for (int q = 0; q < 4; q++) acc2[i][q] = 0ull;

    #pragma unroll 4
    for (int kk = 0; kk < 64; kk++) {
        ulonglong2 bb0 = *(const ulonglong2*)(Bs + kk * DSTRIDE + tx * 8);
        ulonglong2 bb1 = *(const ulonglong2*)(Bs + kk * DSTRIDE + tx * 8 + 4);
        float4 a0 = *(const float4*)(As + kk * DSTRIDE + ty * 8);
        float4 a1 = *(const float4*)(As + kk * DSTRIDE + ty * 8 + 4);
        float a[8] = {a0.x, a0.y, a0.z, a0.w, a1.x, a1.y, a1.z, a1.w};
        #pragma unroll
        for (int i = 0; i < 8; i++) {
            unsigned long long ap = dup2(a[i]);
            fma2(acc2[i][0], ap, bb0.x);
            fma2(acc2[i][1], ap, bb0.y);
            fma2(acc2[i][2], ap, bb1.x);
            fma2(acc2[i][3], ap, bb1.y);
        }
    }

    float sqj[8];
    #pragma unroll
    for (int j = 0; j < 8; j++) sqj[j] = g_sqs[b * 256 + j0 + tx * 8 + j];
    #pragma unroll
    for (int i = 0; i < 8; i++) {
        float sqi = g_sq[b * Nn + i0 + ty * 8 + i];
        float* dst = g_sdist + (size_t)(b * Nn + i0 + ty * 8 + i) * 256 + j0 + tx * 8;
        float2 p0 = unpk(acc2[i][0]);
        float2 p1 = unpk(acc2[i][1]);
        float2 p2 = unpk(acc2[i][2]);
        float2 p3 = unpk(acc2[i][3]);
        float4 r0, r1;
        r0.x = 2.f * p0.x - sqi - sqj[0];
        r0.y = 2.f * p0.y - sqi - sqj[1];
        r0.z = 2.f * p1.x - sqi - sqj[2];
        r0.w = 2.f * p1.y - sqi - sqj[3];
        r1.x = 2.f * p2.x - sqi - sqj[4];
        r1.y = 2.f * p2.y - sqi - sqj[5];
        r1.z = 2.f * p3.x - sqi - sqj[6];
        r1.w = 2.f * p3.y - sqi - sqj[7];
        *(float4*)dst = r0;
        *(float4*)(dst + 4) = r1;
    }
}

// ---------------- kernel 2b: per-row threshold = 12th largest sample ------
__global__ __launch_bounds__(256) void k_thr() {
    int lane = threadIdx.x & 31;
    int row  = blockIdx.x * 8 + (threadIdx.x >> 5);
    const float* sd = g_sdist + (size_t)row * 256;
    float lv[8];
    #pragma unroll
    for (int s = 0; s < 8; s++) lv[s] = sd[lane + 32 * s];
    for (int k = 0; ; k++) {
        float lmax = lv[0];
        #pragma unroll
        for (int s = 1; s < 8; s++) lmax = fmaxf(lmax, lv[s]);
        unsigned key = f2key(lmax);
        unsigned m = __reduce_max_sync(0xffffffffu, key);
        if (k == 11) { if (lane == 0) g_thr[row] = key2f(m); break; }
        int win = __ffs(__ballot_sync(0xffffffffu, key == m)) - 1;
        if (lane == win) {
            bool done = false;
            #pragma unroll
            for (int s = 0; s < 8; s++)
                if (!done && lv[s] == lmax) { lv[s] = -INFINITY; done = true; }
        }
    }
}

// ---------------- kernel 3: symmetric dist GEMM + fixed-slot filter -------
// Upper-triangle tiles only (jb >= ib). After the mainloop, the 2*acc tile
// is staged in smem (stride 129: conflict-free row AND column reads). Each
// warp scans 16 rows (i-side) and 16 columns (j-side), writing survivors
// directly to reserved per-(row,tile) global slots: tile tj of row in block
// bi is owned by block (bi,tj) i-side if tj>=bi, else (tj,bi) j-side —
// exactly one writer per segment, so NO atomics anywhere. Per-segment
// counts go to g_tc; count > SEG is detected in k_sel -> exact fallback.
#define VST 129
__global__ __launch_bounds__(256) void k_dist_sym(const float* __restrict__ x) {
    extern __shared__ float sm[];
    float* As = sm;
    float* Bs = sm + 64 * DSTRIDE;
    __shared__ float s_thri[128], s_thrj[128], s_sqi[128], s_sqj[128];

    const int b  = blockIdx.z;
    const int ib = blockIdx.y;
    const int jb = blockIdx.x;
    if (jb < ib) return;
    const int i0 = ib * 128;
    const int j0 = jb * 128;
    const bool diag = (ib == jb);
    const int tid  = threadIdx.x;
    const int wid  = tid >> 5;
    const int lane = tid & 31;
    const float* xb = x + (size_t)b * Cc * Nn;

    for (int L = tid; L < 2048; L += 256) {
        int c = L >> 5, q = L & 31;
        float4 v = *(const float4*)(xb + c * Nn + i0 + q * 4);
        *(float4*)(As + c * DSTRIDE + q * 4) = v;
        float4 w = *(const float4*)(xb + c * Nn + j0 + q * 4);
        *(float4*)(Bs + c * DSTRIDE + q * 4) = w;
    }
    if (tid < 128) {
        s_thri[tid] = g_thr[b * Nn + i0 + tid];
        s_sqi[tid]  = g_sq [b * Nn + i0 + tid];
    } else {
        int t = tid - 128;
        s_thrj[t] = g_thr[b * Nn + j0 + t];
        s_sqj[t]  = g_sq [b * Nn + j0 + t];
    }
    __syncthreads();

    int tx = tid & 15, ty = tid >> 4;
    unsigned long long acc2[8][4];
    #pragma unroll
    for (int i = 0; i < 8; i++)
        #pragma unroll
        for (int q = 0; q < 4; q++) acc2[i][q] = 0ull;

    #pragma unroll 4
    for (int kk = 0; kk < 64; kk++) {
        ulonglong2 bb0 = *(const ulonglong2*)(Bs + kk * DSTRIDE + tx * 8);
        ulonglong2 bb1 = *(const ulonglong2*)(Bs + kk * DSTRIDE + tx * 8 + 4);
        float4 a0 = *(const float4*)(As + kk * DSTRIDE + ty * 8);
        float4 a1 = *(const float4*)(As + kk * DSTRIDE + ty * 8 + 4);
        float a[8] = {a0.x, a0.y, a0.z, a0.w, a1.x, a1.y, a1.z, a1.w};
        #pragma unroll
        for (int i = 0; i < 8; i++) {
            unsigned long long ap = dup2(a[i]);
            fma2(acc2[i][0], ap, bb0.x);
            fma2(acc2[i][1], ap, bb0.y);
            fma2(acc2[i][2], ap, bb1.x);
            fma2(acc2[i][3], ap, bb1.y);
        }
    }

    // stage 2*acc tile into smem (reuse As/Bs; 128*129 <= 2*64*132)
    __syncthreads();
    float* Vs = sm;
    #pragma unroll
    for (int i = 0; i < 8; i++) {
        int rl = ty * 8 + i;
        float2 q0 = unpk(acc2[i][0]);
        float2 q1 = unpk(acc2[i][1]);
        float2 q2 = unpk(acc2[i][2]);
        float2 q3 = unpk(acc2[i][3]);
        float* vr = Vs + rl * VST + tx * 8;
        vr[0] = 2.f * q0.x; vr[1] = 2.f * q0.y;
        vr[2] = 2.f * q1.x; vr[3] = 2.f * q1.y;
        vr[4] = 2.f * q2.x; vr[5] = 2.f * q2.y;
        vr[6] = 2.f * q3.x; vr[7] = 2.f * q3.y;
    }
    __syncthreads();

    // i-side: warp scans rows wid*16..+15 (this block owns segment jb)
    for (int rr = 0; rr < 16; rr++) {
        int r = wid * 16 + rr;
        float sqi = s_sqi[r], thr = s_thri[r];
        float v[4]; unsigned msk[4]; int pc[4];
        int cnt = 0;
        #pragma unroll
        for (int s = 0; s < 4; s++) {
            int c = lane + 32 * s;
            float t2 = Vs[r * VST + c];
            v[s] = (t2 - sqi) - s_sqj[c];
            msk[s] = __ballot_sync(0xffffffffu, v[s] > thr);
            pc[s] = cnt; cnt += __popc(msk[s]);
        }
        int grow = b * Nn + i0 + r;
        if (lane == 0) g_tc[grow * NTILE + jb] = cnt;
        if (cnt) {
            size_t base = (size_t)grow * CAND_SLOTS + jb * SEG;
            #pragma unroll
            for (int s = 0; s < 4; s++) {
                if ((msk[s] >> lane) & 1u) {
                    int pos = pc[s] + __popc(msk[s] & ((1u << lane) - 1u));
                    if (pos < SEG) {
                        g_candv[base + pos] = v[s];
                        g_candi[base + pos] = j0 + lane + 32 * s;
                    }
                }
            }
        }
    }

    // j-side: warp scans columns wid*16..+15 (this block owns segment ib)
    if (!diag) {
        for (int cc = 0; cc < 16; cc++) {
            int c = wid * 16 + cc;
            float sqj = s_sqj[c], thr = s_thrj[c];
            float v[4]; unsigned msk[4]; int pc[4];
            int cnt = 0;
            #pragma unroll
            for (int s = 0; s < 4; s++) {
                int r = lane + 32 * s;
                float t2 = Vs[r * VST + c];
                v[s] = (t2 - sqj) - s_sqi[r];
                msk[s] = __ballot_sync(0xffffffffu, v[s] > thr);
                pc[s] = cnt; cnt += __popc(msk[s]);
            }
            int grow = b * Nn + j0 + c;
            if (lane == 0) g_tc[grow * NTILE + ib] = cnt;
            if (cnt) {
                size_t base = (size_t)grow * CAND_SLOTS + ib * SEG;
                #pragma unroll
                for (int s = 0; s < 4; s++) {
                    if ((msk[s] >> lane) & 1u) {
                        int pos = pc[s] + __popc(msk[s] & ((1u << lane) - 1u));
                        if (pos < SEG) {
                            g_candv[base + pos] = v[s];
                            g_candi[base + pos] = i0 + lane + 32 * s;
                        }
                    }
                }
            }
        }
    }
}

// ---------------- kernel 4: top-20 select (warp/row, count-compacted) -----
// Per-row: read 64 segment counts, warp-scan to dense offsets, gather the
// ~400 real survivors into a dense smem buffer (values + indices), then
// redux-based extraction. No sentinel scans; validity comes from counts.
__global__ __launch_bounds__(256) void k_sel() {
    extern __shared__ float dsm[];
    int lane = threadIdx.x & 31;
    int w    = threadIdx.x >> 5;
    int row  = blockIdx.x * 8 + w;
    float* dv = dsm + (size_t)w * (2 * DCAP);
    int*   di = (int*)(dv + DCAP);

    const int* tc = g_tc + row * NTILE;
    int c0 = tc[lane];
    int c1 = tc[lane + 32];
    bool ovf = (c0 > SEG) || (c1 > SEG);
    ovf = __any_sync(0xffffffffu, ovf);

    // inclusive warp scans -> dense offsets
    int s0 = c0, s1 = c1;
    #pragma unroll
    for (int off = 1; off < 32; off <<= 1) {
        int y0 = __shfl_up_sync(0xffffffffu, s0, off);
        int y1 = __shfl_up_sync(0xffffffffu, s1, off);
        if (lane >= off) { s0 += y0; s1 += y1; }
    }
    int total0 = __shfl_sync(0xffffffffu, s0, 31);
    int total1 = __shfl_sync(0xffffffffu, s1, 31);
    int n = total0 + total1;
    int d0 = s0 - c0;
    int d1 = total0 + s1 - c1;

    if (!ovf && n >= Kk && n <= DCAP) {
        size_t rb = (size_t)row * CAND_SLOTS;
        const float* gv = g_candv + rb;
        const int*   gi = g_candi + rb;
        for (int e = 0; e < c0; e++) {
            dv[d0 + e] = gv[lane * SEG + e];
            di[d0 + e] = gi[lane * SEG + e];
        }
        for (int e = 0; e < c1; e++) {
            dv[d1 + e] = gv[(lane + 32) * SEG + e];
            di[d1 + e] = gi[(lane + 32) * SEG + e];
        }
        __syncwarp();

        int nseg = (n + 31) >> 5;
        float bv = -INFINITY; int bs = -1;
        for (int s = 0; s < nseg; s++) {
            int c = lane + (s << 5);
            if (c < n) { float vv = dv[c]; if (vv > bv) { bv = vv; bs = c; } }
        }
        for (int k = 0; k < Kk; k++) {
            unsigned key = f2key(bv);
            unsigned m = __reduce_max_sync(0xffffffffu, key);
            int cand = (key == m && bs >= 0) ? di[bs] : 0x7fffffff;
            int widx = __reduce_min_sync(0xffffffffu, cand);
            if (lane == 0) g_idx[row * Kk + k] = widx;
            if (cand == widx) {
                dv[bs] = -INFINITY;
                bv = -INFINITY; bs = -1;
                for (int s = 0; s < nseg; s++) {
                    int c = lane + (s << 5);
                    if (c < n) { float vv = dv[c]; if (vv > bv) { bv = vv; bs = c; } }
                }
            }
        }
    } else {
        // exact warp-local fallback: recompute the row (statistically never)
        int base = (row >> 13) * Nn;
        const float* xq = g_xt + (size_t)row * Cc;
        float sqq = g_sq[row];
        int chosen[Kk];
        for (int k = 0; k < Kk; k++) {
            float bv = -INFINITY; int bi = 0x7fffffff;
            for (int j = lane; j < Nn; j += 32) {
                bool skip = false;
                for (int q = 0; q < k; q++) if (chosen[q] == j) skip = true;
                if (skip) continue;
                const float* xj = g_xt + (size_t)(base + j) * Cc;
                float dot = 0.f;
                #pragma unroll
                for (int c = 0; c < Cc; c++) dot += xq[c] * xj[c];
                float val = 2.f * dot - sqq - g_sq[base + j];
                if (val > bv) { bv = val; bi = j; }
            }
            unsigned key = f2key(bv);
            unsigned m = __reduce_max_sync(0xffffffffu, key);
            int cand = (key == m) ? bi : 0x7fffffff;
            int widx = __reduce_min_sync(0xffffffffu, cand);
            if (lane == 0) g_idx[row * Kk + k] = widx;
            chosen[k] = widx;
        }
    }
}

// ---------------- kernel 5: center term u = (W[:,C:]-W[:,:C]) . cen -------
__global__ void k_u(const float* __restrict__ W) {
    __shared__ float Wd[64 * 65];   // [c][o], stride 65 (conflict-free)
    __shared__ float cs[4 * 64];
    int tid = threadIdx.x;
    for (int L = tid; L < 4096; L += 256) {
        int c = L & 63, o = L >> 6;
        Wd[c * 65 + o] = W[o * 128 + 64 + c] - W[o * 128 + c];
    }
    int p0 = blockIdx.x * 4;
    {
        int pi = tid >> 6, c = tid & 63;
        cs[pi * 64 + c] = g_xt[(size_t)(p0 + pi) * 64 + c];
    }
    __syncthreads();
    int o = tid & 63, pi = tid >> 6;
    float a = 0.f;
    #pragma unroll
    for (int c = 0; c < 64; c++) a += Wd[c * 65 + o] * cs[pi * 64 + c];
    g_u[(size_t)(p0 + pi) * 64 + o] = a;
}

// ---------------- kernel 6/8: gathered GEMM  h = A·nbr + u ----------------
#define SA 161
#define WS_OFF 10400   // floats (41600 B region for As/hbuf)
template<int MODE>
__global__ void k_conv(const float* __restrict__ W, float* __restrict__ out) {
    extern __shared__ float sm[];
    float* As = sm;            // [64][161]  (MODE1: reused as hbuf [160][65])
    float* Ws = sm + WS_OFF;   // [64][68]
    __shared__ int   rowb[160];
    __shared__ int   ub[160];
    __shared__ float ssum[64];
    __shared__ float ssq[64];
    __shared__ float ssc[64];
    __shared__ float ssh[64];

    int tid = threadIdx.x;
    int m0 = blockIdx.x * 160;

    if (tid < 160) {
        int m = m0 + tid;
        int nb = g_idx[m];
        int pt = m / Kk;           // global point index b*N+n
        int b  = pt >> 13;
        rowb[tid] = b * Nn + nb;   // gathered xt row
        ub[tid]   = pt;            // u row
    }
    for (int L = tid; L < 4096; L += 256) {
        int c = L & 63, o = L >> 6;
        Ws[c * 68 + o] = W[o * 128 + c];   // A part, K-major
    }
    if (MODE == 0) { if (tid < 64) { ssum[tid] = 0.f; ssq[tid] = 0.f; } }
    else           { if (tid < 64) { ssc[tid] = g_sc[tid]; ssh[tid] = g_sh[tid]; } }
    __syncthreads();

    for (int L = tid; L < 2560; L += 256) {
        int r = L >> 4, c4 = L & 15;
        float4 v = *(const float4*)(g_xt + (size_t)rowb[r] * 64 + c4 * 4);
        As[(c4 * 4 + 0) * SA + r] = v.x;
        As[(c4 * 4 + 1) * SA + r] = v.y;
        As[(c4 * 4 + 2) * SA + r] = v.z;
        As[(c4 * 4 + 3) * SA + r] = v.w;
    }
    __syncthreads();

    int tx = tid & 7, ty = tid >> 3;   // tx: 8 col-groups, ty: 32 row-groups
    float acc[5][8];
    #pragma unroll
    for (int i = 0; i < 5; i++)
        #pragma unroll
        for (int j = 0; j < 8; j++) acc[i][j] = 0.f;

    #pragma unroll 4
    for (int kk = 0; kk < 64; kk++) {
        float a[5];
        #pragma unroll
        for (int i = 0; i < 5; i++) a[i] = As[kk * SA + ty * 5 + i];
        float4 b0 = *(float4*)(Ws + kk * 68 + tx * 8);
        float4 b1 = *(float4*)(Ws + kk * 68 + tx * 8 + 4);
        float bbv[8] = {b0.x, b0.y, b0.z, b0.w, b1.x, b1.y, b1.z, b1.w};
        #pragma unroll
        for (int i = 0; i < 5; i++)
            #pragma unroll
            for (int j = 0; j < 8; j++) acc[i][j] += a[i] * bbv[j];
    }

    // add center term
    float hv[5][8];
    #pragma unroll
    for (int i = 0; i < 5; i++) {
        const float* up = g_u + (size_t)ub[ty * 5 + i] * 64 + tx * 8;
        float4 u0 = *(const float4*)up;
        float4 u1 = *(const float4*)(up + 4);
        float uv[8] = {u0.x, u0.y, u0.z, u0.w, u1.x, u1.y, u1.z, u1.w};
        #pragma unroll
        for (int j = 0; j < 8; j++) hv[i][j] = acc[i][j] + uv[j];
    }

    if (MODE == 0) {
        float ps[8], pq[8];
        #pragma unroll
        for (int j = 0; j < 8; j++) { ps[j] = 0.f; pq[j] = 0.f; }
        #pragma unroll
        for (int i = 0; i < 5; i++)
            #pragma unroll
            for (int j = 0; j < 8; j++) {
                float v = hv[i][j];
                ps[j] += v; pq[j] += v * v;
            }
        #pragma unroll
        for (int j = 0; j < 8; j++) {
            atomicAdd(&ssum[tx * 8 + j], ps[j]);
            atomicAdd(&ssq [tx * 8 + j], pq[j]);
        }
        __syncthreads();
        if (tid < 64) {
            atomicAdd(&g_sum[tid],   (double)ssum[tid]);
            atomicAdd(&g_sumsq[tid], (double)ssq[tid]);
        }
    } else {
        __syncthreads();  // As fully consumed; safe to reuse as hbuf
        #pragma unroll
        for (int i = 0; i < 5; i++)
            #pragma unroll
            for (int j = 0; j < 8; j++) {
                int o = tx * 8 + j;
                float v = hv[i][j] * ssc[o] + ssh[o];
                v = (v >= 0.f) ? v : 0.2f * v;
                As[(ty * 5 + i) * 65 + o] = v;
            }
        __syncthreads();
        for (int task = tid; task < 512; task += 256) {
            int p = task >> 6, o = task & 63;
            float mx = -INFINITY;
            #pragma unroll
            for (int k = 0; k < Kk; k++)
                mx = fmaxf(mx, As[(p * Kk + k) * 65 + o]);
            int pt = m0 / Kk + p;
            int b = pt >> 13, n = pt & (Nn - 1);
            out[((size_t)b * 64 + o) * Nn + n] = mx;
        }
    }
}

// ---------------- kernel 7: finalize BN scale/shift ----------------
__global__ void k_fin(const float* __restrict__ gamma, const float* __restrict__ beta) {
    int o = threadIdx.x;
    if (o < Oo) {
        double cnt  = (double)MROWS;
        double mean = g_sum[o] / cnt;
        double var  = g_sumsq[o] / cnt - mean * mean;
        float inv = rsqrtf((float)(var + 1e-5));
        float sc  = gamma[o] * inv;
        g_sc[o] = sc;
        g_sh[o] = beta[o] - (float)mean * sc;
    }
}

// ---------------- launcher ----------------
extern "C" void kernel_launch(void* const* d_in, const int* in_sizes, int n_in,
                              void* d_out, int out_size) {
    const float* x     = (const float*)d_in[0];
    const float* W     = (const float*)d_in[1];
    const float* gamma = (const float*)d_in[2];
    const float* beta  = (const float*)d_in[3];
    float* out = (float*)d_out;

    const int SMEM_GEMM = 2 * 64 * DSTRIDE * sizeof(float);          // 67584
    const int SMEM_SEL  = 8 * 2 * DCAP * sizeof(float);              // 98304
    const int SMEM_CONV = (WS_OFF + 64 * 68) * sizeof(float);        // 59008

    cudaFuncSetAttribute(k_samp,     cudaFuncAttributeMaxDynamicSharedMemorySize, SMEM_GEMM);
    cudaFuncSetAttribute(k_dist_sym, cudaFuncAttributeMaxDynamicSharedMemorySize, SMEM_GEMM);
    cudaFuncSetAttribute(k_sel,      cudaFuncAttributeMaxDynamicSharedMemorySize, SMEM_SEL);
    cudaFuncSetAttribute(k_conv<0>,  cudaFuncAttributeMaxDynamicSharedMemorySize, SMEM_CONV);
    cudaFuncSetAttribute(k_conv<1>,  cudaFuncAttributeMaxDynamicSharedMemorySize, SMEM_CONV);

    k_zero<<<1, 64>>>();
    k_prep<<<NPOINTS / 256, 256>>>(x);
    k_samp<<<dim3(2, Nn / 128, Bb), 256, SMEM_GEMM>>>(x);
    k_thr<<<NPOINTS / 8, 256>>>();
    k_dist_sym<<<dim3(Nn / 128, Nn / 128, Bb), 256, SMEM_GEMM>>>(x);
    k_sel<<<NPOINTS / 8, 256, SMEM_SEL>>>();
    k_u<<<NPOINTS / 4, 256>>>(W);
    k_conv<0><<<NBLK_CONV, 256, SMEM_CONV>>>(W, out);
    k_fin<<<1, 64>>>(gamma, beta);
    k_conv<1><<<NBLK_CONV, 256, SMEM_CONV>>>(W, out);
}